// round 3
// baseline (speedup 1.0000x reference)
#include <cuda_runtime.h>
#include <float.h>

#define NN   8192   // nodes per graph
#define DF   128    // feature dim
#define NA   512    // anchors
#define KSEL 32     // top-K
#define TA   32     // anchors per CTA tile
#define TN   128    // nodes per CTA tile
#define DC   32     // d chunk

// Scratch (allocation-free rule: __device__ globals)
__device__ float g_dist[2][NA][NN];   // 32MB distance matrices
__device__ float g_D[NA];             // margin-augmented positive distances

__device__ __forceinline__ unsigned long long addf32x2(unsigned long long a,
                                                       unsigned long long b) {
    unsigned long long r;
    asm("add.rn.f32x2 %0, %1, %2;" : "=l"(r) : "l"(a), "l"(b));
    return r;
}

// ---------------------------------------------------------------------------
// Kernel A: D[a] = L1(out1[anchor1[a]], out2[anchor2[a]]) + MARGIN; zero d_out
// ---------------------------------------------------------------------------
__global__ __launch_bounds__(256) void prep_kernel(
    const float* __restrict__ out1, const float* __restrict__ out2,
    const int* __restrict__ anchor1, const int* __restrict__ anchor2,
    float* out)
{
    int tid  = blockIdx.x * blockDim.x + threadIdx.x;
    if (tid == 0) out[0] = 0.0f;          // d_out is poisoned; zero it for atomics
    int a    = tid >> 5;
    int lane = tid & 31;
    if (a >= NA) return;
    const float4* r1 = (const float4*)(out1 + (size_t)anchor1[a] * DF);
    const float4* r2 = (const float4*)(out2 + (size_t)anchor2[a] * DF);
    float4 v1 = r1[lane];
    float4 v2 = r2[lane];
    float s = fabsf(v1.x - v2.x) + fabsf(v1.y - v2.y)
            + fabsf(v1.z - v2.z) + fabsf(v1.w - v2.w);
    #pragma unroll
    for (int o = 16; o; o >>= 1) s += __shfl_xor_sync(0xffffffffu, s, o);
    if (lane == 0) g_D[a] = s + 1.0f;
}

// ---------------------------------------------------------------------------
// Kernel B: tiled L1 cdist with packed f32x2 math.
// A tile stored as (even,odd)-d float2 pairs per anchor; B tile NEGATED and
// packed the same way. Inner loop per 2 d-steps:
//   t = add.f32x2(a, -b); t &= abs-mask (2x LOP3, alu pipe); acc = add.f32x2.
// fma-pipe and alu-pipe each carry half the work -> ~2x vs scalar FADD chain.
// Lane j-mapping {l, l+32, l+64, l+96} keeps packed B loads contiguous LDS.64.
// ---------------------------------------------------------------------------
__global__ __launch_bounds__(256) void dist_kernel(
    const float* __restrict__ out1, const float* __restrict__ out2,
    const int* __restrict__ anchor1, const int* __restrict__ anchor2)
{
    __shared__ __align__(16) float2 Ast2[DF / 2][TA + 1];   // [d-pair][anchor]
    __shared__ __align__(16) float2 Bs2[DC / 2][TN + 2];    // [d-pair][node], negated

    int dir = blockIdx.z;
    const float* Asrc = dir ? out2 : out1;
    const float* Bsrc = dir ? out1 : out2;
    const int*   anc  = dir ? anchor2 : anchor1;
    int a_base = blockIdx.y * TA;
    int n_base = blockIdx.x * TN;
    int tid  = threadIdx.x;

    // Load + transpose-pack A tile: 32 anchor rows x 128 d -> 64 pair-rows
    {
        int a  = tid >> 3;        // 0..31
        int dq = tid & 7;         // float4 index within a 32-d chunk
        const float4* src = (const float4*)(Asrc + (size_t)anc[a_base + a] * DF);
        #pragma unroll
        for (int c = 0; c < 4; c++) {
            float4 v = src[dq + 8 * c];
            int r = (dq << 1) + (c << 4);            // pair-row = d/2
            Ast2[r + 0][a] = make_float2(v.x, v.y);
            Ast2[r + 1][a] = make_float2(v.z, v.w);
        }
    }

    int warp = tid >> 5, lane = tid & 31;
    int a0 = warp << 2;           // 8 warps x 4 anchors = 32

    unsigned long long acc[4][4];
    #pragma unroll
    for (int i = 0; i < 4; i++)
        #pragma unroll
        for (int j = 0; j < 4; j++) acc[i][j] = 0ULL;

    for (int dc = 0; dc < DF; dc += DC) {
        __syncthreads();   // protects Bs2 reuse (and Ast2 stores on first pass)
        // Load + transpose-pack-NEGATE B chunk: 128 node rows x 32 d
        #pragma unroll
        for (int p = 0; p < 4; p++) {
            int l  = (p << 8) + tid;     // 0..1023 float4s
            int n  = l >> 3;
            int dq = l & 7;
            float4 v = *(const float4*)(Bsrc + (size_t)(n_base + n) * DF + dc + (dq << 2));
            int r = dq << 1;
            Bs2[r + 0][n] = make_float2(-v.x, -v.y);
            Bs2[r + 1][n] = make_float2(-v.z, -v.w);
        }
        __syncthreads();

        int dbase = dc >> 1;
        #pragma unroll
        for (int dd2 = 0; dd2 < DC / 2; dd2++) {
            unsigned long long ap[4], bp[4];
            #pragma unroll
            for (int i = 0; i < 4; i++)          // broadcast LDS.64
                ap[i] = *(const unsigned long long*)&Ast2[dbase + dd2][a0 + i];
            #pragma unroll
            for (int j = 0; j < 4; j++)          // contiguous LDS.64
                bp[j] = *(const unsigned long long*)&Bs2[dd2][lane + (j << 5)];
            #pragma unroll
            for (int i = 0; i < 4; i++)
                #pragma unroll
                for (int j = 0; j < 4; j++) {
                    unsigned long long t = addf32x2(ap[i], bp[j]);  // a + (-b)
                    t &= 0x7FFFFFFF7FFFFFFFULL;                     // |.| per half
                    acc[i][j] = addf32x2(acc[i][j], t);
                }
        }
    }

    #pragma unroll
    for (int i = 0; i < 4; i++)
        #pragma unroll
        for (int j = 0; j < 4; j++) {
            float lo = __uint_as_float((unsigned)(acc[i][j] & 0xFFFFFFFFULL));
            float hi = __uint_as_float((unsigned)(acc[i][j] >> 32));
            g_dist[dir][a_base + a0 + i][n_base + lane + (j << 5)] = lo + hi;
        }
}

// ---------------------------------------------------------------------------
// Kernel C: per row, sum relu(D - d_k) over the 32 smallest of 8192 distances.
// Cached-min scheme: each thread owns 32 strided smem slots and a cached
// (min, slot); per iteration reduce cached mins, only the winner rescans.
// ---------------------------------------------------------------------------
__global__ __launch_bounds__(256) void select_kernel(float* out)
{
    __shared__ float vals[NN];            // 32KB
    __shared__ float wmin[8];
    __shared__ int   wwho[8];
    __shared__ int   s_who;

    int row = blockIdx.x;                 // 0..1023
    int dir = row >> 9;
    int a   = row & (NA - 1);
    int tid = threadIdx.x;
    int lane = tid & 31, warp = tid >> 5;

    const float* src = g_dist[dir][a];
    for (int i = tid; i < NN; i += 256) vals[i] = src[i];
    __syncthreads();

    float cmin = FLT_MAX; int cidx = 0;
    #pragma unroll
    for (int i = 0; i < 32; i++) {
        float v = vals[i * 256 + tid];    // conflict-free strided ownership
        if (v < cmin) { cmin = v; cidx = i; }
    }

    float D = g_D[a];
    float lsum = 0.0f;

    for (int k = 0; k < KSEL; k++) {
        float m = cmin; int who = tid;
        #pragma unroll
        for (int o = 16; o; o >>= 1) {
            float om = __shfl_xor_sync(0xffffffffu, m, o);
            int   ow = __shfl_xor_sync(0xffffffffu, who, o);
            if (om < m) { m = om; who = ow; }
        }
        if (lane == 0) { wmin[warp] = m; wwho[warp] = who; }
        __syncthreads();
        if (tid == 0) {
            float bm = wmin[0]; int bw = wwho[0];
            #pragma unroll
            for (int w = 1; w < 8; w++)
                if (wmin[w] < bm) { bm = wmin[w]; bw = wwho[w]; }
            s_who = bw;
            lsum += fmaxf(D - bm, 0.0f);
        }
        __syncthreads();
        if (tid == s_who) {               // only the winner rescans its 32 slots
            vals[cidx * 256 + tid] = FLT_MAX;
            cmin = FLT_MAX; cidx = 0;
            #pragma unroll
            for (int i = 0; i < 32; i++) {
                float v = vals[i * 256 + tid];
                if (v < cmin) { cmin = v; cidx = i; }
            }
        }
        // next iteration's barrier orders s_who/wmin reuse
    }
    if (tid == 0) atomicAdd(out, lsum * (1.0f / (NA * KSEL)));
}

// ---------------------------------------------------------------------------
extern "C" void kernel_launch(void* const* d_in, const int* in_sizes, int n_in,
                              void* d_out, int out_size)
{
    const float* out1    = (const float*)d_in[0];
    const float* out2    = (const float*)d_in[1];
    const int*   anchor1 = (const int*)d_in[2];
    const int*   anchor2 = (const int*)d_in[3];
    float* out = (float*)d_out;

    prep_kernel<<<64, 256>>>(out1, out2, anchor1, anchor2, out);

    dim3 grid(NN / TN, NA / TA, 2);   // 64 x 16 x 2
    dist_kernel<<<grid, 256>>>(out1, out2, anchor1, anchor2);

    select_kernel<<<2 * NA, 256>>>(out);
}

// round 6
// speedup vs baseline: 1.2164x; 1.2164x over previous
#include <cuda_runtime.h>
#include <cuda_fp16.h>
#include <float.h>

#define NN   8192   // nodes per graph
#define DF   128    // feature dim
#define NA   512    // anchors
#define KSEL 32     // top-K
#define TA   32     // anchors per CTA tile
#define TN   128    // nodes per CTA tile

// Scratch (allocation-free rule: __device__ globals)
__device__ float   g_dist[2][NA][NN];      // 32MB distance matrices
__device__ float   g_D[NA];                // margin-augmented positive distances
__device__ __half2 g_h[2][NN][DF / 2];     // fp16 copies of out1/out2 (4MB)

// ---------------------------------------------------------------------------
// Kernel 0: convert both embedding matrices to fp16 (packed half2 d-pairs).
// Grid 2048 x 256 = 524288 threads = 2 arrays x NN*DF/4 float4s, exact.
// ---------------------------------------------------------------------------
__global__ __launch_bounds__(256) void convert_kernel(
    const float* __restrict__ out1, const float* __restrict__ out2)
{
    int t   = blockIdx.x * 256 + threadIdx.x;     // one float4 per thread
    int arr = t >> 18;                            // NN*DF/4 = 2^18 per array
    int i   = t & ((1 << 18) - 1);
    float4 v = ((const float4*)(arr ? out2 : out1))[i];
    __half2* dst = &g_h[arr][0][0];
    dst[2 * i + 0] = __floats2half2_rn(v.x, v.y);
    dst[2 * i + 1] = __floats2half2_rn(v.z, v.w);
}

// ---------------------------------------------------------------------------
// Kernel A: D[a] = L1(out1[anchor1[a]], out2[anchor2[a]]) + MARGIN (fp32);
// also zeroes d_out for the final atomics.
// ---------------------------------------------------------------------------
__global__ __launch_bounds__(256) void prep_kernel(
    const float* __restrict__ out1, const float* __restrict__ out2,
    const int* __restrict__ anchor1, const int* __restrict__ anchor2,
    float* out)
{
    int tid  = blockIdx.x * blockDim.x + threadIdx.x;
    if (tid == 0) out[0] = 0.0f;
    int a    = tid >> 5;
    int lane = tid & 31;
    if (a >= NA) return;
    const float4* r1 = (const float4*)(out1 + (size_t)anchor1[a] * DF);
    const float4* r2 = (const float4*)(out2 + (size_t)anchor2[a] * DF);
    float4 v1 = r1[lane];
    float4 v2 = r2[lane];
    float s = fabsf(v1.x - v2.x) + fabsf(v1.y - v2.y)
            + fabsf(v1.z - v2.z) + fabsf(v1.w - v2.w);
    #pragma unroll
    for (int o = 16; o; o >>= 1) s += __shfl_xor_sync(0xffffffffu, s, o);
    if (lane == 0) g_D[a] = s + 1.0f;
}

// ---------------------------------------------------------------------------
// Kernel B: tiled L1 cdist in packed fp16.
// Per 2 d-dims per cell: HSUB2 + habs2 + HADD2 -> 2 fma-pipe instrs / 2 elems
// (2x the scalar fp32 FADD rate). Two half2 accumulators per cell (each fp16
// lane sums only 32 terms, <=~50 magnitude) combined in fp32 at the end.
// Cell j maps to node n_base + 4*lane + j -> B loads and the output store are
// contiguous 16B per lane (LDS.128 / STG.128, conflict-free).
// ---------------------------------------------------------------------------
__global__ __launch_bounds__(256) void dist_kernel(
    const int* __restrict__ anchor1, const int* __restrict__ anchor2)
{
    __shared__ __align__(16) __half2 Ast[64][36];    // [d-pair][anchor]
    __shared__ __align__(16) __half2 Bs[16][132];    // [d-pair][node]

    int dir = blockIdx.z;
    const int* anc = dir ? anchor2 : anchor1;
    const __half2* Ah = &g_h[dir ? 1 : 0][0][0];
    const __half2* Bh = &g_h[dir ? 0 : 1][0][0];
    int a_base = blockIdx.y * TA;
    int n_base = blockIdx.x * TN;
    int tid  = threadIdx.x;
    int warp = tid >> 5, lane = tid & 31;
    int a0 = warp << 2;

    // Load + transpose A tile: 32 anchors x 64 d-pairs
    #pragma unroll
    for (int p = 0; p < 2; p++) {
        int l  = (p << 8) + tid;
        int a  = l >> 4;              // 0..31
        int dq = l & 15;              // 16B chunk (4 d-pairs)
        int node = anc[a_base + a];
        uint4 v = ((const uint4*)(Ah + (size_t)node * (DF / 2)))[dq];
        int r = dq << 2;
        *reinterpret_cast<unsigned*>(&Ast[r + 0][a]) = v.x;
        *reinterpret_cast<unsigned*>(&Ast[r + 1][a]) = v.y;
        *reinterpret_cast<unsigned*>(&Ast[r + 2][a]) = v.z;
        *reinterpret_cast<unsigned*>(&Ast[r + 3][a]) = v.w;
    }

    const __half2 hz = __float2half2_rn(0.0f);
    __half2 acc[4][4][2];
    #pragma unroll
    for (int i = 0; i < 4; i++)
        #pragma unroll
        for (int j = 0; j < 4; j++) { acc[i][j][0] = hz; acc[i][j][1] = hz; }

    for (int ch = 0; ch < 4; ch++) {        // 4 chunks of 16 d-pairs
        __syncthreads();
        // Load + transpose B chunk: 128 nodes x 16 d-pairs
        #pragma unroll
        for (int p = 0; p < 2; p++) {
            int l  = (p << 8) + tid;
            int n  = l >> 2;          // 0..127
            int dq = l & 3;           // 16B chunk within the 16 d-pairs
            uint4 v = *(const uint4*)(Bh + (size_t)(n_base + n) * (DF / 2)
                                         + (ch << 4) + (dq << 2));
            int r = dq << 2;
            *reinterpret_cast<unsigned*>(&Bs[r + 0][n]) = v.x;
            *reinterpret_cast<unsigned*>(&Bs[r + 1][n]) = v.y;
            *reinterpret_cast<unsigned*>(&Bs[r + 2][n]) = v.z;
            *reinterpret_cast<unsigned*>(&Bs[r + 3][n]) = v.w;
        }
        __syncthreads();

        int rbase = ch << 4;
        #pragma unroll
        for (int dd = 0; dd < 16; dd++) {
            uint4 av = *(const uint4*)&Ast[rbase + dd][a0];       // broadcast
            uint4 bv = *(const uint4*)&Bs[dd][lane << 2];         // contiguous
            __half2 ap[4], bp[4];
            ap[0] = *reinterpret_cast<__half2*>(&av.x);
            ap[1] = *reinterpret_cast<__half2*>(&av.y);
            ap[2] = *reinterpret_cast<__half2*>(&av.z);
            ap[3] = *reinterpret_cast<__half2*>(&av.w);
            bp[0] = *reinterpret_cast<__half2*>(&bv.x);
            bp[1] = *reinterpret_cast<__half2*>(&bv.y);
            bp[2] = *reinterpret_cast<__half2*>(&bv.z);
            bp[3] = *reinterpret_cast<__half2*>(&bv.w);
            int ph = dd & 1;
            #pragma unroll
            for (int i = 0; i < 4; i++)
                #pragma unroll
                for (int j = 0; j < 4; j++)
                    acc[i][j][ph] = __hadd2(acc[i][j][ph],
                                            __habs2(__hsub2(ap[i], bp[j])));
        }
    }

    // Epilogue: combine 4 fp16 partial lanes in fp32, store float4 per lane.
    #pragma unroll
    for (int i = 0; i < 4; i++) {
        float w[4];
        #pragma unroll
        for (int j = 0; j < 4; j++) {
            float2 s0 = __half22float2(acc[i][j][0]);
            float2 s1 = __half22float2(acc[i][j][1]);
            w[j] = (s0.x + s0.y) + (s1.x + s1.y);
        }
        *(float4*)&g_dist[dir][a_base + a0 + i][n_base + (lane << 2)] =
            make_float4(w[0], w[1], w[2], w[3]);
    }
}

// ---------------------------------------------------------------------------
// Kernel C: per row, sum relu(D - d_k) over the 32 smallest of 8192 distances.
// Cached-min scheme: each thread owns 32 strided smem slots and a cached
// (min, slot); per iteration reduce cached mins, only the winner rescans.
// ---------------------------------------------------------------------------
__global__ __launch_bounds__(256) void select_kernel(float* out)
{
    __shared__ float vals[NN];            // 32KB
    __shared__ float wmin[8];
    __shared__ int   wwho[8];
    __shared__ int   s_who;

    int row = blockIdx.x;                 // 0..1023
    int dir = row >> 9;
    int a   = row & (NA - 1);
    int tid = threadIdx.x;
    int lane = tid & 31, warp = tid >> 5;

    const float* src = g_dist[dir][a];
    for (int i = tid; i < NN; i += 256) vals[i] = src[i];
    __syncthreads();

    float cmin = FLT_MAX; int cidx = 0;
    #pragma unroll
    for (int i = 0; i < 32; i++) {
        float v = vals[i * 256 + tid];    // conflict-free strided ownership
        if (v < cmin) { cmin = v; cidx = i; }
    }

    float D = g_D[a];
    float lsum = 0.0f;

    for (int k = 0; k < KSEL; k++) {
        float m = cmin; int who = tid;
        #pragma unroll
        for (int o = 16; o; o >>= 1) {
            float om = __shfl_xor_sync(0xffffffffu, m, o);
            int   ow = __shfl_xor_sync(0xffffffffu, who, o);
            if (om < m) { m = om; who = ow; }
        }
        if (lane == 0) { wmin[warp] = m; wwho[warp] = who; }
        __syncthreads();
        if (tid == 0) {
            float bm = wmin[0]; int bw = wwho[0];
            #pragma unroll
            for (int w = 1; w < 8; w++)
                if (wmin[w] < bm) { bm = wmin[w]; bw = wwho[w]; }
            s_who = bw;
            lsum += fmaxf(D - bm, 0.0f);
        }
        __syncthreads();
        if (tid == s_who) {               // only the winner rescans its 32 slots
            vals[cidx * 256 + tid] = FLT_MAX;
            cmin = FLT_MAX; cidx = 0;
            #pragma unroll
            for (int i = 0; i < 32; i++) {
                float v = vals[i * 256 + tid];
                if (v < cmin) { cmin = v; cidx = i; }
            }
        }
        // next iteration's barrier orders s_who/wmin reuse
    }
    if (tid == 0) atomicAdd(out, lsum * (1.0f / (NA * KSEL)));
}

// ---------------------------------------------------------------------------
extern "C" void kernel_launch(void* const* d_in, const int* in_sizes, int n_in,
                              void* d_out, int out_size)
{
    const float* out1    = (const float*)d_in[0];
    const float* out2    = (const float*)d_in[1];
    const int*   anchor1 = (const int*)d_in[2];
    const int*   anchor2 = (const int*)d_in[3];
    float* out = (float*)d_out;

    convert_kernel<<<2048, 256>>>(out1, out2);
    prep_kernel<<<64, 256>>>(out1, out2, anchor1, anchor2, out);

    dim3 grid(NN / TN, NA / TA, 2);   // 64 x 16 x 2
    dist_kernel<<<grid, 256>>>(anchor1, anchor2);

    select_kernel<<<2 * NA, 256>>>(out);
}

// round 9
// speedup vs baseline: 1.5573x; 1.2802x over previous
#include <cuda_runtime.h>
#include <cuda_fp16.h>
#include <float.h>

#define NN   8192   // nodes per graph
#define DF   128    // feature dim
#define NA   512    // anchors
#define KSEL 32     // top-K
#define TA   32     // anchors per CTA tile
#define TN   128    // nodes per CTA tile
#define NBIN 256
#define BINSCALE 8.0f     // bin width 0.125, range [rmin, rmin+32)
#define BUFCAP 256

// Scratch (allocation-free rule: __device__ globals)
__device__ float   g_dist[2][NA][NN];      // 32MB distance matrices
__device__ float   g_D[NA];                // margin-augmented positive distances
__device__ __half2 g_h[2][NN][DF / 2];     // fp16 copies of out1/out2 (4MB)

// ---------------------------------------------------------------------------
// Kernel 0: convert both embeddings to fp16 (half2 d-pairs) + fused prep:
// blocks 0..63 additionally compute D[a] = L1(a1,a2) + MARGIN (one warp per
// anchor) and thread 0 zeroes d_out.
// ---------------------------------------------------------------------------
__global__ __launch_bounds__(256) void convert_prep_kernel(
    const float* __restrict__ out1, const float* __restrict__ out2,
    const int* __restrict__ anchor1, const int* __restrict__ anchor2,
    float* out)
{
    int t   = blockIdx.x * 256 + threadIdx.x;     // one float4 per thread
    if (t == 0) out[0] = 0.0f;
    int arr = t >> 18;                            // NN*DF/4 = 2^18 per array
    int i   = t & ((1 << 18) - 1);
    float4 v = ((const float4*)(arr ? out2 : out1))[i];
    __half2* dst = &g_h[arr][0][0];
    dst[2 * i + 0] = __floats2half2_rn(v.x, v.y);
    dst[2 * i + 1] = __floats2half2_rn(v.z, v.w);

    if (blockIdx.x < 64) {                        // fused prep: 64*8 = 512 anchors
        int a    = (blockIdx.x << 3) + (threadIdx.x >> 5);
        int lane = threadIdx.x & 31;
        const float4* r1 = (const float4*)(out1 + (size_t)anchor1[a] * DF);
        const float4* r2 = (const float4*)(out2 + (size_t)anchor2[a] * DF);
        float4 v1 = r1[lane];
        float4 v2 = r2[lane];
        float s = fabsf(v1.x - v2.x) + fabsf(v1.y - v2.y)
                + fabsf(v1.z - v2.z) + fabsf(v1.w - v2.w);
        #pragma unroll
        for (int o = 16; o; o >>= 1) s += __shfl_xor_sync(0xffffffffu, s, o);
        if (lane == 0) g_D[a] = s + 1.0f;
    }
}

// ---------------------------------------------------------------------------
// Kernel B: tiled L1 cdist in packed fp16 (unchanged from R6 — at fma floor).
// ---------------------------------------------------------------------------
__global__ __launch_bounds__(256) void dist_kernel(
    const int* __restrict__ anchor1, const int* __restrict__ anchor2)
{
    __shared__ __align__(16) __half2 Ast[64][36];    // [d-pair][anchor]
    __shared__ __align__(16) __half2 Bs[16][132];    // [d-pair][node]

    int dir = blockIdx.z;
    const int* anc = dir ? anchor2 : anchor1;
    const __half2* Ah = &g_h[dir ? 1 : 0][0][0];
    const __half2* Bh = &g_h[dir ? 0 : 1][0][0];
    int a_base = blockIdx.y * TA;
    int n_base = blockIdx.x * TN;
    int tid  = threadIdx.x;
    int warp = tid >> 5, lane = tid & 31;
    int a0 = warp << 2;

    // Load + transpose A tile: 32 anchors x 64 d-pairs
    #pragma unroll
    for (int p = 0; p < 2; p++) {
        int l  = (p << 8) + tid;
        int a  = l >> 4;              // 0..31
        int dq = l & 15;              // 16B chunk (4 d-pairs)
        int node = anc[a_base + a];
        uint4 v = ((const uint4*)(Ah + (size_t)node * (DF / 2)))[dq];
        int r = dq << 2;
        *reinterpret_cast<unsigned*>(&Ast[r + 0][a]) = v.x;
        *reinterpret_cast<unsigned*>(&Ast[r + 1][a]) = v.y;
        *reinterpret_cast<unsigned*>(&Ast[r + 2][a]) = v.z;
        *reinterpret_cast<unsigned*>(&Ast[r + 3][a]) = v.w;
    }

    const __half2 hz = __float2half2_rn(0.0f);
    __half2 acc[4][4][2];
    #pragma unroll
    for (int i = 0; i < 4; i++)
        #pragma unroll
        for (int j = 0; j < 4; j++) { acc[i][j][0] = hz; acc[i][j][1] = hz; }

    for (int ch = 0; ch < 4; ch++) {        // 4 chunks of 16 d-pairs
        __syncthreads();
        #pragma unroll
        for (int p = 0; p < 2; p++) {
            int l  = (p << 8) + tid;
            int n  = l >> 2;          // 0..127
            int dq = l & 3;
            uint4 v = *(const uint4*)(Bh + (size_t)(n_base + n) * (DF / 2)
                                         + (ch << 4) + (dq << 2));
            int r = dq << 2;
            *reinterpret_cast<unsigned*>(&Bs[r + 0][n]) = v.x;
            *reinterpret_cast<unsigned*>(&Bs[r + 1][n]) = v.y;
            *reinterpret_cast<unsigned*>(&Bs[r + 2][n]) = v.z;
            *reinterpret_cast<unsigned*>(&Bs[r + 3][n]) = v.w;
        }
        __syncthreads();

        int rbase = ch << 4;
        #pragma unroll
        for (int dd = 0; dd < 16; dd++) {
            uint4 av = *(const uint4*)&Ast[rbase + dd][a0];       // broadcast
            uint4 bv = *(const uint4*)&Bs[dd][lane << 2];         // contiguous
            __half2 ap[4], bp[4];
            ap[0] = *reinterpret_cast<__half2*>(&av.x);
            ap[1] = *reinterpret_cast<__half2*>(&av.y);
            ap[2] = *reinterpret_cast<__half2*>(&av.z);
            ap[3] = *reinterpret_cast<__half2*>(&av.w);
            bp[0] = *reinterpret_cast<__half2*>(&bv.x);
            bp[1] = *reinterpret_cast<__half2*>(&bv.y);
            bp[2] = *reinterpret_cast<__half2*>(&bv.z);
            bp[3] = *reinterpret_cast<__half2*>(&bv.w);
            int ph = dd & 1;
            #pragma unroll
            for (int i = 0; i < 4; i++)
                #pragma unroll
                for (int j = 0; j < 4; j++)
                    acc[i][j][ph] = __hadd2(acc[i][j][ph],
                                            __habs2(__hsub2(ap[i], bp[j])));
        }
    }

    #pragma unroll
    for (int i = 0; i < 4; i++) {
        float w[4];
        #pragma unroll
        for (int j = 0; j < 4; j++) {
            float2 s0 = __half22float2(acc[i][j][0]);
            float2 s1 = __half22float2(acc[i][j][1]);
            w[j] = (s0.x + s0.y) + (s1.x + s1.y);
        }
        *(float4*)&g_dist[dir][a_base + a0 + i][n_base + (lane << 2)] =
            make_float4(w[0], w[1], w[2], w[3]);
    }
}

// ---------------------------------------------------------------------------
// Kernel C: exact top-K selection via histogram.
// Per row: values in registers (32/thread); block-min; 256-bin linear
// histogram over [min, min+32); warp-scan finds the threshold bin; one pass
// sums relu(D-v) for bins < t and spills bin-t values (expected 1-3) to a
// tiny list; thread 0 extracts the residual r smallest exactly.
// ---------------------------------------------------------------------------
__global__ __launch_bounds__(256) void select_kernel(float* out)
{
    __shared__ int   hist[NBIN];
    __shared__ float sred[8];
    __shared__ float binvals[BUFCAP];
    __shared__ int   bincnt;
    __shared__ float s_rmin;
    __shared__ int   s_tbin, s_r;

    int row = blockIdx.x;                 // 0..1023
    int dir = row >> 9;
    int a   = row & (NA - 1);
    int tid = threadIdx.x;
    int lane = tid & 31, warp = tid >> 5;

    hist[tid] = 0;
    if (tid == 0) bincnt = 0;

    const float4* src = (const float4*)g_dist[dir][a];
    float v[32];
    #pragma unroll
    for (int i = 0; i < 8; i++) {
        float4 q = src[i * 256 + tid];    // coalesced 128-bit loads
        v[4 * i + 0] = q.x; v[4 * i + 1] = q.y;
        v[4 * i + 2] = q.z; v[4 * i + 3] = q.w;
    }

    // Block min
    float lm = v[0];
    #pragma unroll
    for (int i = 1; i < 32; i++) lm = fminf(lm, v[i]);
    #pragma unroll
    for (int o = 16; o; o >>= 1) lm = fminf(lm, __shfl_xor_sync(0xffffffffu, lm, o));
    if (lane == 0) sred[warp] = lm;
    __syncthreads();
    if (tid == 0) {
        float m = sred[0];
        #pragma unroll
        for (int w = 1; w < 8; w++) m = fminf(m, sred[w]);
        s_rmin = m;
    }
    __syncthreads();
    float rmin = s_rmin;

    // Histogram
    #pragma unroll
    for (int i = 0; i < 32; i++) {
        int b = (int)((v[i] - rmin) * BINSCALE);
        b = b > (NBIN - 1) ? (NBIN - 1) : b;
        atomicAdd(&hist[b], 1);
    }
    __syncthreads();

    // Warp 0: scan 256 bins, find threshold bin t (first with cum >= KSEL)
    if (warp == 0) {
        int base = lane << 3;
        int c[8], s = 0;
        #pragma unroll
        for (int j = 0; j < 8; j++) { c[j] = hist[base + j]; s += c[j]; }
        int pre = s;
        #pragma unroll
        for (int o = 1; o < 32; o <<= 1) {
            int tsc = __shfl_up_sync(0xffffffffu, pre, o);
            if (lane >= o) pre += tsc;
        }
        int excl = pre - s;
        unsigned bal = __ballot_sync(0xffffffffu, excl < KSEL && pre >= KSEL);
        int tl = __ffs(bal) - 1;
        if (lane == tl) {
            int cum = excl, tb = base;
            #pragma unroll
            for (int j = 0; j < 8; j++) {
                if (cum + c[j] >= KSEL) { tb = base + j; break; }
                cum += c[j];
            }
            s_tbin = tb;
            s_r    = KSEL - cum;      // 1..count(tbin)
        }
    }
    __syncthreads();
    int   tbin = s_tbin;
    float D    = g_D[a];

    // Sum relu(D - v) for bins < t; spill bin-t values
    float lsum = 0.0f;
    #pragma unroll
    for (int i = 0; i < 32; i++) {
        int b = (int)((v[i] - rmin) * BINSCALE);
        b = b > (NBIN - 1) ? (NBIN - 1) : b;
        if (b < tbin) lsum += fmaxf(D - v[i], 0.0f);
        else if (b == tbin) {
            int idx = atomicAdd(&bincnt, 1);
            if (idx < BUFCAP) binvals[idx] = v[i];
        }
    }
    #pragma unroll
    for (int o = 16; o; o >>= 1) lsum += __shfl_xor_sync(0xffffffffu, lsum, o);
    __syncthreads();              // sred reuse (min -> sum)
    if (lane == 0) sred[warp] = lsum;
    __syncthreads();

    if (tid == 0) {
        float tot = 0.0f;
        #pragma unroll
        for (int w = 1; w < 8; w++) tot += sred[w];
        tot += sred[0];
        // Extract the r smallest from the threshold bin (tiny list)
        int L = bincnt < BUFCAP ? bincnt : BUFCAP;
        int r = s_r;
        for (int k = 0; k < r; k++) {
            float m = FLT_MAX; int mi = -1;
            for (int q = 0; q < L; q++)
                if (binvals[q] < m) { m = binvals[q]; mi = q; }
            binvals[mi] = FLT_MAX;
            tot += fmaxf(D - m, 0.0f);
        }
        atomicAdd(out, tot * (1.0f / (NA * KSEL)));
    }
}

// ---------------------------------------------------------------------------
extern "C" void kernel_launch(void* const* d_in, const int* in_sizes, int n_in,
                              void* d_out, int out_size)
{
    const float* out1    = (const float*)d_in[0];
    const float* out2    = (const float*)d_in[1];
    const int*   anchor1 = (const int*)d_in[2];
    const int*   anchor2 = (const int*)d_in[3];
    float* out = (float*)d_out;

    convert_prep_kernel<<<2048, 256>>>(out1, out2, anchor1, anchor2, out);

    dim3 grid(NN / TN, NA / TA, 2);   // 64 x 16 x 2
    dist_kernel<<<grid, 256>>>(anchor1, anchor2);

    select_kernel<<<2 * NA, 256>>>(out);
}

// round 11
// speedup vs baseline: 1.6908x; 1.0857x over previous
#include <cuda_runtime.h>
#include <cuda_fp16.h>
#include <float.h>

#define NN   8192   // nodes per graph
#define DF   128    // feature dim
#define NA   512    // anchors
#define KSEL 32     // top-K
#define TA   32     // anchors per CTA tile
#define TN   128    // nodes per CTA tile
#define NBIN 256
#define BINSCALE 8.0f     // bin width 0.125, range [rmin, rmin+32)
#define BUFCAP 256

// Scratch (allocation-free rule: __device__ globals)
__device__ __half g_dist16[2][NA][NN];     // 16MB fp16 distance matrices

// ---------------------------------------------------------------------------
// Kernel B: tiled L1 cdist in packed fp16, reading fp32 inputs directly
// (fp32->half2 conversion fused into the smem transpose fill).
// Per 2 d-dims per cell: HSUB2 + |.| + HADD2 on the fma pipe (at the packed
// fp16 issue floor). Two half2 accumulators per cell (each fp16 lane sums
// only 32 terms) combined in fp32, stored as fp16.
// Block (0,0,0) thread 0 also zeroes d_out for select's atomics.
// ---------------------------------------------------------------------------
__global__ __launch_bounds__(256) void dist_kernel(
    const float* __restrict__ out1, const float* __restrict__ out2,
    const int* __restrict__ anchor1, const int* __restrict__ anchor2,
    float* out)
{
    __shared__ __align__(16) __half2 Ast[64][36];    // [d-pair][anchor]
    __shared__ __align__(16) __half2 Bs[16][132];    // [d-pair][node]

    int dir = blockIdx.z;
    const int*   anc  = dir ? anchor2 : anchor1;
    const float* Asrc = dir ? out2 : out1;
    const float* Bsrc = dir ? out1 : out2;
    int a_base = blockIdx.y * TA;
    int n_base = blockIdx.x * TN;
    int tid  = threadIdx.x;
    int warp = tid >> 5, lane = tid & 31;
    int a0 = warp << 2;

    if (tid == 0 && blockIdx.x == 0 && blockIdx.y == 0 && blockIdx.z == 0)
        out[0] = 0.0f;

    // Load + convert + transpose A tile: 32 anchors x 128 fp32 dims
    {
        int a  = tid >> 3;            // 0..31
        int dq = tid & 7;             // float4 slot
        const float4* src = (const float4*)(Asrc + (size_t)anc[a_base + a] * DF);
        #pragma unroll
        for (int c = 0; c < 4; c++) {
            float4 v = src[dq + 8 * c];
            int r = ((dq + 8 * c) << 1);      // d-pair row
            Ast[r + 0][a] = __floats2half2_rn(v.x, v.y);
            Ast[r + 1][a] = __floats2half2_rn(v.z, v.w);
        }
    }

    const __half2 hz = __float2half2_rn(0.0f);
    __half2 acc[4][4][2];
    #pragma unroll
    for (int i = 0; i < 4; i++)
        #pragma unroll
        for (int j = 0; j < 4; j++) { acc[i][j][0] = hz; acc[i][j][1] = hz; }

    for (int ch = 0; ch < 4; ch++) {        // 4 chunks of 32 fp32 dims
        __syncthreads();
        // Load + convert + transpose B chunk: 128 nodes x 32 dims
        #pragma unroll
        for (int p = 0; p < 4; p++) {
            int l  = (p << 8) + tid;          // 0..1023 float4s
            int n  = l >> 3;                  // 0..127
            int dq = l & 7;
            float4 v = *(const float4*)(Bsrc + (size_t)(n_base + n) * DF
                                             + (ch << 5) + (dq << 2));
            int r = dq << 1;
            Bs[r + 0][n] = __floats2half2_rn(v.x, v.y);
            Bs[r + 1][n] = __floats2half2_rn(v.z, v.w);
        }
        __syncthreads();

        #pragma unroll
        for (int dd = 0; dd < 16; dd++) {
            uint4 av = *(const uint4*)&Ast[(ch << 4) + dd][a0];   // broadcast
            uint4 bv = *(const uint4*)&Bs[dd][lane << 2];         // contiguous
            __half2 ap[4], bp[4];
            ap[0] = *reinterpret_cast<__half2*>(&av.x);
            ap[1] = *reinterpret_cast<__half2*>(&av.y);
            ap[2] = *reinterpret_cast<__half2*>(&av.z);
            ap[3] = *reinterpret_cast<__half2*>(&av.w);
            bp[0] = *reinterpret_cast<__half2*>(&bv.x);
            bp[1] = *reinterpret_cast<__half2*>(&bv.y);
            bp[2] = *reinterpret_cast<__half2*>(&bv.z);
            bp[3] = *reinterpret_cast<__half2*>(&bv.w);
            int ph = dd & 1;
            #pragma unroll
            for (int i = 0; i < 4; i++)
                #pragma unroll
                for (int j = 0; j < 4; j++)
                    acc[i][j][ph] = __hadd2(acc[i][j][ph],
                                            __habs2(__hsub2(ap[i], bp[j])));
        }
    }

    // Epilogue: combine 4 fp16 partial lanes in fp32, store 4 halves (8B/lane)
    #pragma unroll
    for (int i = 0; i < 4; i++) {
        float w[4];
        #pragma unroll
        for (int j = 0; j < 4; j++) {
            float2 s0 = __half22float2(acc[i][j][0]);
            float2 s1 = __half22float2(acc[i][j][1]);
            w[j] = (s0.x + s0.y) + (s1.x + s1.y);
        }
        __half2 h01 = __floats2half2_rn(w[0], w[1]);
        __half2 h23 = __floats2half2_rn(w[2], w[3]);
        __half2* dst = (__half2*)&g_dist16[dir][a_base + a0 + i][n_base + (lane << 2)];
        dst[0] = h01;
        dst[1] = h23;       // together: one STG.64, coalesced across lanes
    }
}

// ---------------------------------------------------------------------------
// Kernel C: exact top-K via histogram, with D computed in-block (warp 0).
// Values (32/thread) live in registers; 256-bin linear histogram over
// [min, min+32); warp-scan finds the threshold bin; one pass sums
// relu(D-v) below it and spills threshold-bin values to a tiny list.
// ---------------------------------------------------------------------------
__global__ __launch_bounds__(256) void select_kernel(
    const float* __restrict__ out1, const float* __restrict__ out2,
    const int* __restrict__ anchor1, const int* __restrict__ anchor2,
    float* out)
{
    __shared__ int   hist[NBIN];
    __shared__ float sred[8];
    __shared__ float binvals[BUFCAP];
    __shared__ int   bincnt;
    __shared__ float s_rmin, s_D;
    __shared__ int   s_tbin, s_r;

    int row = blockIdx.x;                 // 0..1023
    int dir = row >> 9;
    int a   = row & (NA - 1);
    int tid = threadIdx.x;
    int lane = tid & 31, warp = tid >> 5;

    hist[tid] = 0;
    if (tid == 0) bincnt = 0;

    // Warp 0: compute D = L1(out1[anchor1[a]], out2[anchor2[a]]) + 1
    if (warp == 0) {
        const float4* r1 = (const float4*)(out1 + (size_t)anchor1[a] * DF);
        const float4* r2 = (const float4*)(out2 + (size_t)anchor2[a] * DF);
        float4 v1 = r1[lane];
        float4 v2 = r2[lane];
        float s = fabsf(v1.x - v2.x) + fabsf(v1.y - v2.y)
                + fabsf(v1.z - v2.z) + fabsf(v1.w - v2.w);
        #pragma unroll
        for (int o = 16; o; o >>= 1) s += __shfl_xor_sync(0xffffffffu, s, o);
        if (lane == 0) s_D = s + 1.0f;
    }

    // Load 32 fp16 distances per thread (4x uint4 = 8 halves each), coalesced
    const uint4* src = (const uint4*)g_dist16[dir][a];
    float v[32];
    #pragma unroll
    for (int i = 0; i < 4; i++) {
        uint4 q = src[i * 256 + tid];
        const unsigned u[4] = {q.x, q.y, q.z, q.w};
        #pragma unroll
        for (int j = 0; j < 4; j++) {
            float2 f = __half22float2(*reinterpret_cast<const __half2*>(&u[j]));
            v[8 * i + 2 * j + 0] = f.x;
            v[8 * i + 2 * j + 1] = f.y;
        }
    }

    // Block min
    float lm = v[0];
    #pragma unroll
    for (int i = 1; i < 32; i++) lm = fminf(lm, v[i]);
    #pragma unroll
    for (int o = 16; o; o >>= 1) lm = fminf(lm, __shfl_xor_sync(0xffffffffu, lm, o));
    if (lane == 0) sred[warp] = lm;
    __syncthreads();
    if (tid == 0) {
        float m = sred[0];
        #pragma unroll
        for (int w = 1; w < 8; w++) m = fminf(m, sred[w]);
        s_rmin = m;
    }
    __syncthreads();
    float rmin = s_rmin;

    // Histogram
    #pragma unroll
    for (int i = 0; i < 32; i++) {
        int b = (int)((v[i] - rmin) * BINSCALE);
        b = b > (NBIN - 1) ? (NBIN - 1) : b;
        atomicAdd(&hist[b], 1);
    }
    __syncthreads();

    // Warp 0: scan 256 bins, find threshold bin t (first with cum >= KSEL)
    if (warp == 0) {
        int base = lane << 3;
        int c[8], s = 0;
        #pragma unroll
        for (int j = 0; j < 8; j++) { c[j] = hist[base + j]; s += c[j]; }
        int pre = s;
        #pragma unroll
        for (int o = 1; o < 32; o <<= 1) {
            int tsc = __shfl_up_sync(0xffffffffu, pre, o);
            if (lane >= o) pre += tsc;
        }
        int excl = pre - s;
        unsigned bal = __ballot_sync(0xffffffffu, excl < KSEL && pre >= KSEL);
        int tl = __ffs(bal) - 1;
        if (lane == tl) {
            int cum = excl, tb = base;
            #pragma unroll
            for (int j = 0; j < 8; j++) {
                if (cum + c[j] >= KSEL) { tb = base + j; break; }
                cum += c[j];
            }
            s_tbin = tb;
            s_r    = KSEL - cum;      // 1..count(tbin)
        }
    }
    __syncthreads();
    int   tbin = s_tbin;
    float D    = s_D;

    // Sum relu(D - v) for bins < t; spill bin-t values
    float lsum = 0.0f;
    #pragma unroll
    for (int i = 0; i < 32; i++) {
        int b = (int)((v[i] - rmin) * BINSCALE);
        b = b > (NBIN - 1) ? (NBIN - 1) : b;
        if (b < tbin) lsum += fmaxf(D - v[i], 0.0f);
        else if (b == tbin) {
            int idx = atomicAdd(&bincnt, 1);
            if (idx < BUFCAP) binvals[idx] = v[i];
        }
    }
    #pragma unroll
    for (int o = 16; o; o >>= 1) lsum += __shfl_xor_sync(0xffffffffu, lsum, o);
    __syncthreads();              // sred reuse (min -> sum)
    if (lane == 0) sred[warp] = lsum;
    __syncthreads();

    if (tid == 0) {
        float tot = 0.0f;
        #pragma unroll
        for (int w = 0; w < 8; w++) tot += sred[w];
        // Extract the r smallest from the threshold bin (tiny list)
        int L = bincnt < BUFCAP ? bincnt : BUFCAP;
        int r = s_r;
        for (int k = 0; k < r; k++) {
            float m = FLT_MAX; int mi = -1;
            for (int q = 0; q < L; q++)
                if (binvals[q] < m) { m = binvals[q]; mi = q; }
            binvals[mi] = FLT_MAX;
            tot += fmaxf(D - m, 0.0f);
        }
        atomicAdd(out, tot * (1.0f / (NA * KSEL)));
    }
}

// ---------------------------------------------------------------------------
extern "C" void kernel_launch(void* const* d_in, const int* in_sizes, int n_in,
                              void* d_out, int out_size)
{
    const float* out1    = (const float*)d_in[0];
    const float* out2    = (const float*)d_in[1];
    const int*   anchor1 = (const int*)d_in[2];
    const int*   anchor2 = (const int*)d_in[3];
    float* out = (float*)d_out;

    dim3 grid(NN / TN, NA / TA, 2);   // 64 x 16 x 2
    dist_kernel<<<grid, 256>>>(out1, out2, anchor1, anchor2, out);

    select_kernel<<<2 * NA, 256>>>(out1, out2, anchor1, anchor2, out);
}

// round 16
// speedup vs baseline: 2.6546x; 1.5700x over previous
#include <cuda_runtime.h>
#include <cuda_fp16.h>
#include <float.h>

#define NN   8192   // nodes per graph
#define DF   128    // feature dim
#define NA   512    // anchors
#define KSEL 32     // top-K
#define CSEL 48     // candidate shortlist size (safety margin over KSEL)
#define TA   32     // anchors per CTA tile
#define TN   128    // nodes per CTA tile
#define NBIN 256
#define BINSCALE 8.0f     // bin width 0.125, histogrammed range [rmin, rmin+32)
#define BUFCAP 256
#define QS   24.0f        // int8 quant scale
#define QINV (1.0f / (QS))

// Scratch (allocation-free rule: __device__ globals)
__device__ __half    g_dist16[2][NA][NN];   // 16MB quantized distance matrices
__device__ unsigned  g_q[2][NN][DF / 4];    // int8-packed features (2MB)

// ---------------------------------------------------------------------------
// Kernel 0: quantize both embeddings to int8 (4 dims packed per uint32).
// Thread 0 zeroes d_out for select's atomics.
// ---------------------------------------------------------------------------
__global__ __launch_bounds__(256) void quant_kernel(
    const float* __restrict__ out1, const float* __restrict__ out2, float* out)
{
    int t   = blockIdx.x * 256 + threadIdx.x;
    if (t == 0) out[0] = 0.0f;
    int arr = t >> 18;                     // NN*DF/4 = 2^18 per array
    int i   = t & ((1 << 18) - 1);
    float4 v = ((const float4*)(arr ? out2 : out1))[i];
    int q0 = __float2int_rn(fminf(fmaxf(v.x * QS, -127.f), 127.f));
    int q1 = __float2int_rn(fminf(fmaxf(v.y * QS, -127.f), 127.f));
    int q2 = __float2int_rn(fminf(fmaxf(v.z * QS, -127.f), 127.f));
    int q3 = __float2int_rn(fminf(fmaxf(v.w * QS, -127.f), 127.f));
    (&g_q[arr][0][0])[i] = (unsigned)(q0 & 0xFF)
                         | ((unsigned)(q1 & 0xFF) << 8)
                         | ((unsigned)(q2 & 0xFF) << 16)
                         | ((unsigned)(q3 & 0xFF) << 24);
}

// ---------------------------------------------------------------------------
// Kernel B: tiled L1 cdist in int8 SIMD (candidate-search precision only).
// Per 4 d-dims per cell: __vabsdiffs4 (alu pipe) + __dp4a (fma pipe) run in
// parallel pipes at 0.25 instr/elem each. Full d=128 in one smem pass.
// ---------------------------------------------------------------------------
__global__ __launch_bounds__(256) void dist_kernel(
    const int* __restrict__ anchor1, const int* __restrict__ anchor2)
{
    __shared__ __align__(16) unsigned As[DF / 4][36];    // [d-group][anchor]
    __shared__ __align__(16) unsigned Bs[DF / 4][132];   // [d-group][node]

    int dir = blockIdx.z;
    const int*      anc = dir ? anchor2 : anchor1;
    const unsigned* Aq  = &g_q[dir ? 1 : 0][0][0];
    const unsigned* Bq  = &g_q[dir ? 0 : 1][0][0];
    int a_base = blockIdx.y * TA;
    int n_base = blockIdx.x * TN;
    int tid  = threadIdx.x;
    int warp = tid >> 5, lane = tid & 31;
    int a0 = warp << 2;

    // Load + transpose A tile: 32 anchors x 32 d-groups (128B/anchor)
    {
        int a  = tid >> 3;            // 0..31
        int dq = tid & 7;             // uint4 slot (4 d-groups)
        uint4 v = ((const uint4*)(Aq + (size_t)anc[a_base + a] * (DF / 4)))[dq];
        int g = dq << 2;
        As[g + 0][a] = v.x; As[g + 1][a] = v.y;
        As[g + 2][a] = v.z; As[g + 3][a] = v.w;
    }
    // Load + transpose B tile: 128 nodes x 32 d-groups
    #pragma unroll
    for (int p = 0; p < 4; p++) {
        int l  = (p << 8) + tid;      // 0..1023 uint4s
        int n  = l >> 3;
        int dq = l & 7;
        uint4 v = ((const uint4*)(Bq + (size_t)(n_base + n) * (DF / 4)))[dq];
        int g = dq << 2;
        Bs[g + 0][n] = v.x; Bs[g + 1][n] = v.y;
        Bs[g + 2][n] = v.z; Bs[g + 3][n] = v.w;
    }
    __syncthreads();

    unsigned acc[4][4];
    #pragma unroll
    for (int i = 0; i < 4; i++)
        #pragma unroll
        for (int j = 0; j < 4; j++) acc[i][j] = 0u;

    #pragma unroll
    for (int g = 0; g < DF / 4; g++) {
        uint4 av = *(const uint4*)&As[g][a0];          // warp-broadcast LDS.128
        uint4 bv = *(const uint4*)&Bs[g][lane << 2];   // contiguous LDS.128
        unsigned ap[4] = {av.x, av.y, av.z, av.w};
        unsigned bp[4] = {bv.x, bv.y, bv.z, bv.w};
        #pragma unroll
        for (int i = 0; i < 4; i++)
            #pragma unroll
            for (int j = 0; j < 4; j++)
                acc[i][j] = __dp4a(__vabsdiffs4(ap[i], bp[j]),
                                   0x01010101u, acc[i][j]);
    }

    #pragma unroll
    for (int i = 0; i < 4; i++) {
        __half2 h01 = __floats2half2_rn((float)acc[i][0] * QINV,
                                        (float)acc[i][1] * QINV);
        __half2 h23 = __floats2half2_rn((float)acc[i][2] * QINV,
                                        (float)acc[i][3] * QINV);
        __half2* dst = (__half2*)&g_dist16[dir][a_base + a0 + i][n_base + (lane << 2)];
        dst[0] = h01;
        dst[1] = h23;
    }
}

// ---------------------------------------------------------------------------
// Kernel C: candidate shortlist from quantized distances + EXACT fp32 rescore.
// 1. histogram quantized distances below rmin+32 (256 bins — covers d48's
//    Gumbel tail; the rmin+16 range of R13/R14 is the failure that cost
//    whole relu terms on outlier-min rows)
// 2. threshold bin at cum >= CSEL; spill all (value, index) below its edge
// 3. rescore candidates exactly in fp32 (one warp per candidate, coalesced)
// 4. parallel O(C^2) ranking with index tie-break; sum relu(D - d) for the
//    32 exact-smallest.
// ---------------------------------------------------------------------------
__global__ __launch_bounds__(256) void select_kernel(
    const float* __restrict__ out1, const float* __restrict__ out2,
    const int* __restrict__ anchor1, const int* __restrict__ anchor2,
    float* out)
{
    __shared__ int    hist[NBIN];
    __shared__ float  sred[8];
    __shared__ float  cval[BUFCAP];
    __shared__ int    cidx[BUFCAP];
    __shared__ float  cexact[BUFCAP];
    __shared__ __align__(16) float af[DF];
    __shared__ int    bincnt;
    __shared__ float  s_rmin, s_D;
    __shared__ int    s_tbin;

    int row = blockIdx.x;                 // 0..1023
    int dir = row >> 9;
    int a   = row & (NA - 1);
    int tid = threadIdx.x;
    int lane = tid & 31, warp = tid >> 5;

    hist[tid] = 0;
    if (tid == 0) { bincnt = 0; s_tbin = NBIN - 1; }

    const float* arow = dir ? (out2 + (size_t)anchor2[a] * DF)
                            : (out1 + (size_t)anchor1[a] * DF);
    const float* brows = dir ? out1 : out2;   // candidate feature source

    // Warp 0: D = L1(out1[anchor1[a]], out2[anchor2[a]]) + 1  (fp32 exact)
    if (warp == 0) {
        const float4* r1 = (const float4*)(out1 + (size_t)anchor1[a] * DF);
        const float4* r2 = (const float4*)(out2 + (size_t)anchor2[a] * DF);
        float4 v1 = r1[lane];
        float4 v2 = r2[lane];
        float s = fabsf(v1.x - v2.x) + fabsf(v1.y - v2.y)
                + fabsf(v1.z - v2.z) + fabsf(v1.w - v2.w);
        #pragma unroll
        for (int o = 16; o; o >>= 1) s += __shfl_xor_sync(0xffffffffu, s, o);
        if (lane == 0) s_D = s + 1.0f;
    }
    // Warp 1: stage anchor features for rescoring
    if (warp == 1)
        ((float4*)af)[lane] = ((const float4*)arow)[lane];

    // Load 32 quantized fp16 distances/thread as 16 packed half2, coalesced
    const uint4* src = (const uint4*)g_dist16[dir][a];
    uint4 q[4];
    #pragma unroll
    for (int i = 0; i < 4; i++) q[i] = src[i * 256 + tid];
    const __half2* h = reinterpret_cast<const __half2*>(&q[0]);

    // Block min
    __half2 m2 = h[0];
    #pragma unroll
    for (int i = 1; i < 16; i++) m2 = __hmin2(m2, h[i]);
    float lm = fminf(__low2float(m2), __high2float(m2));
    #pragma unroll
    for (int o = 16; o; o >>= 1) lm = fminf(lm, __shfl_xor_sync(0xffffffffu, lm, o));
    if (lane == 0) sred[warp] = lm;
    __syncthreads();
    if (tid == 0) {
        float m = sred[0];
        #pragma unroll
        for (int w = 1; w < 8; w++) m = fminf(m, sred[w]);
        s_rmin = m;
    }
    __syncthreads();
    float rmin = s_rmin;
    float vcut = rmin + (float)NBIN / BINSCALE;   // rmin + 32

    // Prefiltered histogram (~40% of values; spread over 256 bins)
    #pragma unroll
    for (int i = 0; i < 16; i++) {
        float2 f = __half22float2(h[i]);
        if (f.x < vcut) atomicAdd(&hist[(int)((f.x - rmin) * BINSCALE)], 1);
        if (f.y < vcut) atomicAdd(&hist[(int)((f.y - rmin) * BINSCALE)], 1);
    }
    __syncthreads();

    // Warp 0: threshold bin = first bin with cumulative count >= CSEL
    if (warp == 0) {
        int base = lane << 3;
        int c[8], s = 0;
        #pragma unroll
        for (int j = 0; j < 8; j++) { c[j] = hist[base + j]; s += c[j]; }
        int pre = s;
        #pragma unroll
        for (int o = 1; o < 32; o <<= 1) {
            int tsc = __shfl_up_sync(0xffffffffu, pre, o);
            if (lane >= o) pre += tsc;
        }
        int excl = pre - s;
        unsigned bal = __ballot_sync(0xffffffffu, excl < CSEL && pre >= CSEL);
        if (bal) {
            int tl = __ffs(bal) - 1;
            if (lane == tl) {
                int cum = excl, tb = base;
                #pragma unroll
                for (int j = 0; j < 8; j++) {
                    if (cum + c[j] >= CSEL) { tb = base + j; break; }
                    cum += c[j];
                }
                s_tbin = tb;
            }
        }
    }
    __syncthreads();
    float bhi = rmin + (float)(s_tbin + 1) / BINSCALE;   // spill cut

    // Spill all candidates (quantized value below bhi) with node indices
    #pragma unroll
    for (int i = 0; i < 4; i++) {
        #pragma unroll
        for (int j = 0; j < 4; j++) {
            unsigned u = (&q[i].x)[j];
            float2 f = __half22float2(*reinterpret_cast<const __half2*>(&u));
            int gbase = ((i * 256 + tid) << 3) + (j << 1);
            if (f.x < bhi) {
                int p = atomicAdd(&bincnt, 1);
                if (p < BUFCAP) { cval[p] = f.x; cidx[p] = gbase; }
            }
            if (f.y < bhi) {
                int p = atomicAdd(&bincnt, 1);
                if (p < BUFCAP) { cval[p] = f.y; cidx[p] = gbase + 1; }
            }
        }
    }
    __syncthreads();
    int C = bincnt < BUFCAP ? bincnt : BUFCAP;

    // Exact fp32 rescore: one warp per candidate, lanes cover the 128-d row
    for (int c = warp; c < C; c += 8) {
        const float4* nrow = (const float4*)(brows + (size_t)cidx[c] * DF);
        float4 v = nrow[lane];
        float4 u = ((const float4*)af)[lane];
        float s = fabsf(u.x - v.x) + fabsf(u.y - v.y)
                + fabsf(u.z - v.z) + fabsf(u.w - v.w);
        #pragma unroll
        for (int o = 16; o; o >>= 1) s += __shfl_xor_sync(0xffffffffu, s, o);
        if (lane == 0) cexact[c] = s;
    }
    __syncthreads();

    // Parallel ranking: thread tid ranks candidate tid; top-KSEL contribute
    float D = s_D;
    float lsum = 0.0f;
    if (tid < C) {
        float xi = cexact[tid];
        int rank = 0;
        for (int j = 0; j < C; j++) {
            float xj = cexact[j];
            rank += (xj < xi) || (xj == xi && j < tid);
        }
        if (rank < KSEL) lsum = fmaxf(D - xi, 0.0f);
    }
    #pragma unroll
    for (int o = 16; o; o >>= 1) lsum += __shfl_xor_sync(0xffffffffu, lsum, o);
    __syncthreads();              // sred reuse
    if (lane == 0) sred[warp] = lsum;
    __syncthreads();

    if (tid == 0) {
        float tot = 0.0f;
        #pragma unroll
        for (int w = 0; w < 8; w++) tot += sred[w];
        atomicAdd(out, tot * (1.0f / (NA * KSEL)));
    }
}

// ---------------------------------------------------------------------------
extern "C" void kernel_launch(void* const* d_in, const int* in_sizes, int n_in,
                              void* d_out, int out_size)
{
    const float* out1    = (const float*)d_in[0];
    const float* out2    = (const float*)d_in[1];
    const int*   anchor1 = (const int*)d_in[2];
    const int*   anchor2 = (const int*)d_in[3];
    float* out = (float*)d_out;

    quant_kernel<<<2048, 256>>>(out1, out2, out);

    dim3 grid(NN / TN, NA / TA, 2);   // 64 x 16 x 2
    dist_kernel<<<grid, 256>>>(anchor1, anchor2);

    select_kernel<<<2 * NA, 256>>>(out1, out2, anchor1, anchor2, out);
}